// round 1
// baseline (speedup 1.0000x reference)
#include <cuda_runtime.h>
#include <math.h>

// ---------------------------------------------------------------------------
// PointFeatureAlignment:  3-NN inverse-distance interpolation fused with
// scatter + 8x8 average pooling, reformulated as:
//   W[b, cell, g]  (accumulated 3-NN weights / 64)   then
//   Out[b, d, cell] = sum_g W[b,cell,g] * F[b,g,d]   (dense GEMM, K=512)
// ---------------------------------------------------------------------------

#define IMAGE_SIZE 224
#define MAX_W_ELEMS (4 * 784 * 512)   // B * Ho*Ho * G worst case for this problem
#define MAX_FLAGS   8192

__device__ float g_W[MAX_W_ELEMS];
__device__ int   g_flag[MAX_FLAGS];

// ---------------------------------------------------------------------------
// Kernel 0: zero scratch
// ---------------------------------------------------------------------------
__global__ void zero_kernel(int nW, int nF) {
    int i = blockIdx.x * blockDim.x + threadIdx.x;
    int stride = gridDim.x * blockDim.x;
    // vectorized zero of W (nW is multiple of 4 here: G=512 divisible by 4)
    int nW4 = nW >> 2;
    float4* w4 = reinterpret_cast<float4*>(g_W);
    for (int j = i; j < nW4; j += stride) w4[j] = make_float4(0.f, 0.f, 0.f, 0.f);
    for (int j = i; j < nF; j += stride) g_flag[j] = 0;
}

// ---------------------------------------------------------------------------
// Kernel 1: per-point 3-NN over G centers, accumulate weights into g_W
// grid: (ceil(N/256), B), block 256
// smem: G float4 (x, y, z, |s|^2)
// ---------------------------------------------------------------------------
__global__ void nn_kernel(const float* __restrict__ centers,  // (B, G, 3)
                          const float* __restrict__ points,   // (B, N, 3)
                          const int*   __restrict__ nzidx,    // (N)
                          int G, int N, int Ho, int ks) {
    extern __shared__ float4 sc[];   // G entries
    const int b = blockIdx.y;

    const float* cb = centers + (size_t)b * G * 3;
    for (int g = threadIdx.x; g < G; g += blockDim.x) {
        float x = cb[g * 3 + 0];
        float y = cb[g * 3 + 1];
        float z = cb[g * 3 + 2];
        sc[g] = make_float4(x, y, z, x * x + y * y + z * z);
    }
    __syncthreads();

    int n = blockIdx.x * blockDim.x + threadIdx.x;
    if (n >= N) return;

    const float* p = points + ((size_t)b * N + n) * 3;
    float tx = p[0], ty = p[1], tz = p[2];
    float ax = -2.0f * tx, ay = -2.0f * ty, az = -2.0f * tz;
    float tt = tx * tx + ty * ty + tz * tz;

    // track 3 smallest of d' = |s|^2 - 2 t.s  (constant offset tt added later;
    // strict < keeps earliest index on ties, matching lax.top_k)
    float e0 = 3.4e38f, e1 = 3.4e38f, e2 = 3.4e38f;
    int   i0 = 0, i1 = 0, i2 = 0;

#pragma unroll 4
    for (int g = 0; g < G; g++) {
        float4 c = sc[g];
        float d = fmaf(ax, c.x, fmaf(ay, c.y, fmaf(az, c.z, c.w)));
        if (d < e2) {
            if (d < e1) {
                e2 = e1; i2 = i1;
                if (d < e0) { e1 = e0; i1 = i0; e0 = d; i0 = g; }
                else        { e1 = d;  i1 = g; }
            } else {
                e2 = d; i2 = g;
            }
        }
    }

    float d0 = fmaxf(e0 + tt, 1e-10f);
    float d1 = fmaxf(e1 + tt, 1e-10f);
    float d2 = fmaxf(e2 + tt, 1e-10f);
    float r0 = 1.0f / d0, r1 = 1.0f / d1, r2 = 1.0f / d2;
    float inv = 1.0f / ((r0 + r1 + r2) * (float)(ks * ks));

    int idx = nzidx[n];                       // position in 224*224 image
    int row = idx / IMAGE_SIZE;
    int col = idx - row * IMAGE_SIZE;
    int cell = (row / ks) * Ho + (col / ks);

    float* Wrow = g_W + ((size_t)b * Ho * Ho + cell) * G;
    atomicAdd(Wrow + i0, r0 * inv);
    atomicAdd(Wrow + i1, r1 * inv);
    atomicAdd(Wrow + i2, r2 * inv);
    g_flag[b * Ho * Ho + cell] = 1;           // redundant stores are fine
}

// ---------------------------------------------------------------------------
// Kernel 2: Out[b, d, cell] = sum_g W[b,cell,g] * F[b,g,d]
// Register-tiled SIMT GEMM: CTA tile 64 dims x 64 cells, thread 4x4, K-chunk 16.
// Empty cell tiles (no flag set) short-circuit to zero output.
// grid: (ceil(HoHo/64), ceil(Dim/64), B), block 256
// ---------------------------------------------------------------------------
#define TD 64
#define TC 64
#define KB 16

__global__ void gemm_kernel(const float* __restrict__ F,   // (B, G, Dim)
                            float* __restrict__ out,       // (B, Dim, HoHo)
                            int G, int Dim, int HoHo) {
    __shared__ float Fs[KB][TD + 4];
    __shared__ float Ws[KB][TC + 4];
    __shared__ int s_any;

    const int b  = blockIdx.z;
    const int d0 = blockIdx.y * TD;
    const int c0 = blockIdx.x * TC;
    const int tid = threadIdx.x;

    if (tid == 0) s_any = 0;
    __syncthreads();
    if (tid < TC) {
        int c = c0 + tid;
        if (c < HoHo && g_flag[b * HoHo + c]) s_any = 1;   // benign race
    }
    __syncthreads();

    const int ty = tid >> 4;   // 0..15 : dim direction
    const int tx = tid & 15;   // 0..15 : cell direction

    float acc[4][4];
#pragma unroll
    for (int i = 0; i < 4; i++)
#pragma unroll
        for (int j = 0; j < 4; j++) acc[i][j] = 0.f;

    if (s_any) {
        const float* Fb = F + (size_t)b * G * Dim;
        const float* Wb = g_W + (size_t)b * HoHo * G;

        for (int g0 = 0; g0 < G; g0 += KB) {
            // --- load F tile: rows kk (16) x dims dd (64) ---
            {
                int kk = tid >> 6;       // 0..3
                int dd = tid & 63;
#pragma unroll
                for (int r = 0; r < 4; r++) {
                    int k = kk + r * 4;
                    int d = d0 + dd;
                    Fs[k][dd] = (d < Dim) ? Fb[(size_t)(g0 + k) * Dim + d] : 0.f;
                }
            }
            // --- load W tile: cells cc (64) x k (16), vectorized over k ---
            {
                int cc = tid & 63;
                int kq = tid >> 6;       // 0..3
                int c = c0 + cc;
                float4 w4 = make_float4(0.f, 0.f, 0.f, 0.f);
                if (c < HoHo)
                    w4 = *reinterpret_cast<const float4*>(Wb + (size_t)c * G + g0 + kq * 4);
                Ws[kq * 4 + 0][cc] = w4.x;
                Ws[kq * 4 + 1][cc] = w4.y;
                Ws[kq * 4 + 2][cc] = w4.z;
                Ws[kq * 4 + 3][cc] = w4.w;
            }
            __syncthreads();

#pragma unroll
            for (int kk = 0; kk < KB; kk++) {
                float4 av = *reinterpret_cast<const float4*>(&Fs[kk][ty * 4]);
                float4 bv = *reinterpret_cast<const float4*>(&Ws[kk][tx * 4]);
                float a[4] = {av.x, av.y, av.z, av.w};
                float bb[4] = {bv.x, bv.y, bv.z, bv.w};
#pragma unroll
                for (int i = 0; i < 4; i++)
#pragma unroll
                    for (int j = 0; j < 4; j++)
                        acc[i][j] = fmaf(a[i], bb[j], acc[i][j]);
            }
            __syncthreads();
        }
    }

    // --- store (also writes zeros for empty tiles -> full output coverage) ---
#pragma unroll
    for (int i = 0; i < 4; i++) {
        int d = d0 + ty * 4 + i;
        if (d < Dim) {
            float* orow = out + ((size_t)b * Dim + d) * HoHo;
#pragma unroll
            for (int j = 0; j < 4; j++) {
                int c = c0 + tx * 4 + j;
                if (c < HoHo) orow[c] = acc[i][j];
            }
        }
    }
}

// ---------------------------------------------------------------------------
// Launch
// ---------------------------------------------------------------------------
extern "C" void kernel_launch(void* const* d_in, const int* in_sizes, int n_in,
                              void* d_out, int out_size) {
    const float* group_features = (const float*)d_in[0];  // (B, G, Dim)
    const float* group_centers  = (const float*)d_in[1];  // (B, G, 3)
    const float* original_pts   = (const float*)d_in[2];  // (B, N, 3)
    const int*   nonzero_idx    = (const int*)d_in[3];    // (N)

    const int N   = in_sizes[3];
    const int B   = in_sizes[2] / (3 * N);
    const int Dim = (int)(3LL * in_sizes[0] / in_sizes[1]);
    const int G   = in_sizes[1] / (3 * B);
    const int HoHo = out_size / (B * Dim);
    int Ho = 1;
    while ((Ho + 1) * (Ho + 1) <= HoHo) Ho++;     // integer sqrt
    const int ks = IMAGE_SIZE / Ho;

    const int nW = B * HoHo * G;
    const int nF = B * HoHo;

    zero_kernel<<<512, 256>>>(nW, nF);

    dim3 nnGrid((N + 255) / 256, B);
    size_t smem = (size_t)G * sizeof(float4);
    nn_kernel<<<nnGrid, 256, smem>>>(group_centers, original_pts, nonzero_idx,
                                     G, N, Ho, ks);

    dim3 gGrid((HoHo + TC - 1) / TC, (Dim + TD - 1) / TD, B);
    gemm_kernel<<<gGrid, 256>>>(group_features, (float*)d_out, G, Dim, HoHo);
}

// round 3
// speedup vs baseline: 1.1529x; 1.1529x over previous
#include <cuda_runtime.h>
#include <cstdint>
#include <math.h>
#include <mma.h>

using namespace nvcuda;

// ---------------------------------------------------------------------------
// PointFeatureAlignment:  3-NN inverse-distance interpolation fused with
// scatter + 8x8 average pooling, reformulated as:
//   W[b, cell, g]  (accumulated 3-NN weights / 64)   then
//   Out[b, d, cell] = sum_g W[b,cell,g] * F[b,g,d]
// GEMM on wmma tf32 tensor cores (baseline PTX; tcgen05 unavailable because
// the harness emits .target sm_103 without the 'a' feature suffix).
// ---------------------------------------------------------------------------

#define IMAGE_SIZE 224
#define MAX_W_ELEMS (4 * 784 * 512)

__device__ float g_W[MAX_W_ELEMS];

__device__ __forceinline__ uint32_t smem_u32(const void* p) {
    uint32_t a;
    asm("{ .reg .u64 t; cvta.to.shared.u64 t, %1; cvt.u32.u64 %0, t; }"
        : "=r"(a) : "l"(p));
    return a;
}

__device__ __forceinline__ void cp_async16(uint32_t dst, const void* src, int src_bytes) {
    asm volatile("cp.async.ca.shared.global [%0], [%1], 16, %2;"
                 :: "r"(dst), "l"(src), "r"(src_bytes) : "memory");
}
__device__ __forceinline__ void cp_commit() {
    asm volatile("cp.async.commit_group;" ::: "memory");
}

// ---------------------------------------------------------------------------
// Kernel 0: zero W scratch
// ---------------------------------------------------------------------------
__global__ void zero_kernel(int nW) {
    int i = blockIdx.x * blockDim.x + threadIdx.x;
    int stride = gridDim.x * blockDim.x;
    int nW4 = nW >> 2;
    float4* w4 = reinterpret_cast<float4*>(g_W);
    for (int j = i; j < nW4; j += stride) w4[j] = make_float4(0.f, 0.f, 0.f, 0.f);
}

// ---------------------------------------------------------------------------
// Kernel 1: per-point 3-NN over G centers, accumulate weights into g_W
// ---------------------------------------------------------------------------
__global__ void nn_kernel(const float* __restrict__ centers,  // (B, G, 3)
                          const float* __restrict__ points,   // (B, N, 3)
                          const int*   __restrict__ nzidx,    // (N)
                          int G, int N, int Ho, int ks) {
    extern __shared__ float4 sc[];   // G entries: (x, y, z, |s|^2)
    const int b = blockIdx.y;

    const float* cb = centers + (size_t)b * G * 3;
    for (int g = threadIdx.x; g < G; g += blockDim.x) {
        float x = cb[g * 3 + 0];
        float y = cb[g * 3 + 1];
        float z = cb[g * 3 + 2];
        sc[g] = make_float4(x, y, z, x * x + y * y + z * z);
    }
    __syncthreads();

    int n = blockIdx.x * blockDim.x + threadIdx.x;
    if (n >= N) return;

    const float* p = points + ((size_t)b * N + n) * 3;
    float tx = p[0], ty = p[1], tz = p[2];
    float ax = -2.0f * tx, ay = -2.0f * ty, az = -2.0f * tz;
    float tt = tx * tx + ty * ty + tz * tz;

    float e0 = 3.4e38f, e1 = 3.4e38f, e2 = 3.4e38f;
    int   i0 = 0, i1 = 0, i2 = 0;

#pragma unroll 4
    for (int g = 0; g < G; g++) {
        float4 c = sc[g];
        float d = fmaf(ax, c.x, fmaf(ay, c.y, fmaf(az, c.z, c.w)));
        if (d < e2) {
            if (d < e1) {
                e2 = e1; i2 = i1;
                if (d < e0) { e1 = e0; i1 = i0; e0 = d; i0 = g; }
                else        { e1 = d;  i1 = g; }
            } else {
                e2 = d; i2 = g;
            }
        }
    }

    float d0 = fmaxf(e0 + tt, 1e-10f);
    float d1 = fmaxf(e1 + tt, 1e-10f);
    float d2 = fmaxf(e2 + tt, 1e-10f);
    float r0 = 1.0f / d0, r1 = 1.0f / d1, r2 = 1.0f / d2;
    float inv = 1.0f / ((r0 + r1 + r2) * (float)(ks * ks));

    int idx = nzidx[n];
    int row = idx / IMAGE_SIZE;
    int col = idx - row * IMAGE_SIZE;
    int cell = (row / ks) * Ho + (col / ks);

    float* Wrow = g_W + ((size_t)b * Ho * Ho + cell) * G;
    atomicAdd(Wrow + i0, r0 * inv);
    atomicAdd(Wrow + i1, r1 * inv);
    atomicAdd(Wrow + i2, r2 * inv);
}

// ---------------------------------------------------------------------------
// Kernel 2: wmma tf32 GEMM
//   Out[b, d0+d, c0+c] = sum_g F[g, d0+d] * W[c0+c, g]
// CTA: 64(d) x 64(c), 4 warps (2x2), warp tile 32x32 (2x2 wmma m16n16k8).
// K chunked at 16, cp.async double-buffered.
// As[k][d] (col-major A view, ldm 72), Bs[n][k] (col-major B view, ldm 24).
// ---------------------------------------------------------------------------
#define KC 16
#define A_LDM 72
#define B_LDM 24
#define A_SZ (KC * A_LDM)     // 1152 floats
#define B_SZ (64 * B_LDM)     // 1536 floats

struct __align__(32) GSmem {
    union {
        struct { float As[2][A_SZ]; float Bs[2][B_SZ]; } b;
        float stage[64 * A_LDM];
    };
};

__global__ void __launch_bounds__(128) gemm_wmma_kernel(
        const float* __restrict__ F,   // (B, G, Dim)
        float* __restrict__ out,       // (B, Dim, HoHo)
        int G, int Dim, int HoHo) {
    __shared__ GSmem sm;

    const int tid = threadIdx.x;
    const int wid = tid >> 5;
    const int wy = wid >> 1;            // d direction (0..1)
    const int wx = wid & 1;             // c direction (0..1)
    const int b  = blockIdx.z;
    const int d0 = blockIdx.y * 64;
    const int c0 = blockIdx.x * 64;

    const float* Fb = F + (size_t)b * G * Dim;
    const float* Wb = g_W + (size_t)b * HoHo * G;

    const uint32_t smA = smem_u32(sm.b.As[0]);
    const uint32_t smB = smem_u32(sm.b.Bs[0]);

    wmma::fragment<wmma::accumulator, 16, 16, 8, float> acc[2][2];
#pragma unroll
    for (int i = 0; i < 2; i++)
#pragma unroll
        for (int j = 0; j < 2; j++) wmma::fill_fragment(acc[i][j], 0.0f);

    auto load_chunk = [&](int c, int buf) {
        const int g0 = c * KC;
        // A: As[k][d] = F[g0+k][d0+d]   (16 rows x 64 floats, 16B granules)
#pragma unroll
        for (int r = 0; r < 2; r++) {
            int op = r * 128 + tid;       // 0..255
            int k  = op >> 4;             // 0..15
            int d4 = op & 15;             // 16B granule in row
            const float* src = Fb + (size_t)(g0 + k) * Dim + d0 + d4 * 4;
            int bytes = (d0 + d4 * 4 + 4 <= Dim) ? 16 : 0;
            cp_async16(smA + (uint32_t)(buf * A_SZ + k * A_LDM + d4 * 4) * 4, src, bytes);
        }
        // B: Bs[n][k] = W[c0+n][g0+k]   (64 rows x 16 floats, 16B granules)
#pragma unroll
        for (int r = 0; r < 2; r++) {
            int op = r * 128 + tid;       // 0..255
            int n  = op >> 2;             // 0..63
            int kq = op & 3;              // 16B granule in row
            const float* src = Wb + (size_t)(c0 + n) * G + g0 + kq * 4;
            int bytes = (c0 + n < HoHo) ? 16 : 0;
            cp_async16(smB + (uint32_t)(buf * B_SZ + n * B_LDM + kq * 4) * 4, src, bytes);
        }
        cp_commit();
    };

    const int NC = G / KC;
    load_chunk(0, 0);

    for (int c = 0; c < NC; c++) {
        const int buf = c & 1;
        if (c + 1 < NC) {
            load_chunk(c + 1, (c + 1) & 1);
            asm volatile("cp.async.wait_group 1;" ::: "memory");
        } else {
            asm volatile("cp.async.wait_group 0;" ::: "memory");
        }
        __syncthreads();

        const float* As = sm.b.As[buf];
        const float* Bs = sm.b.Bs[buf];
#pragma unroll
        for (int ks = 0; ks < KC; ks += 8) {
            wmma::fragment<wmma::matrix_a, 16, 16, 8, wmma::precision::tf32, wmma::col_major> af[2];
            wmma::fragment<wmma::matrix_b, 16, 16, 8, wmma::precision::tf32, wmma::col_major> bf[2];
#pragma unroll
            for (int fi = 0; fi < 2; fi++) {
                wmma::load_matrix_sync(af[fi], As + ks * A_LDM + wy * 32 + fi * 16, A_LDM);
#pragma unroll
                for (int t = 0; t < af[fi].num_elements; t++)
                    af[fi].x[t] = wmma::__float_to_tf32(af[fi].x[t]);
            }
#pragma unroll
            for (int fj = 0; fj < 2; fj++) {
                wmma::load_matrix_sync(bf[fj], Bs + (wx * 32 + fj * 16) * B_LDM + ks, B_LDM);
#pragma unroll
                for (int t = 0; t < bf[fj].num_elements; t++)
                    bf[fj].x[t] = wmma::__float_to_tf32(bf[fj].x[t]);
            }
#pragma unroll
            for (int fi = 0; fi < 2; fi++)
#pragma unroll
                for (int fj = 0; fj < 2; fj++)
                    wmma::mma_sync(acc[fi][fj], af[fi], bf[fj], acc[fi][fj]);
        }
        __syncthreads();
    }

    // --- epilogue: frags -> smem stage -> guarded coalesced global stores ---
#pragma unroll
    for (int fi = 0; fi < 2; fi++)
#pragma unroll
        for (int fj = 0; fj < 2; fj++)
            wmma::store_matrix_sync(
                sm.stage + (wy * 32 + fi * 16) * A_LDM + wx * 32 + fj * 16,
                acc[fi][fj], A_LDM, wmma::mem_row_major);
    __syncthreads();

    {
        const int row = tid >> 1;                 // 0..63 : local d
        const int cb  = (tid & 1) * 32;           // col half base
        const int d = d0 + row;
        if (d < Dim) {
            float* orow = out + ((size_t)b * Dim + d) * HoHo;
            const float* srow = sm.stage + row * A_LDM + cb;
#pragma unroll
            for (int j = 0; j < 32; j += 4) {
                int cc = c0 + cb + j;
                if (cc + 4 <= HoHo) {
                    float4 v = *reinterpret_cast<const float4*>(srow + j);
                    *reinterpret_cast<float4*>(orow + cc) = v;
                } else {
#pragma unroll
                    for (int q = 0; q < 4; q++)
                        if (cc + q < HoHo) orow[cc + q] = srow[j + q];
                }
            }
        }
    }
}

// ---------------------------------------------------------------------------
// Launch
// ---------------------------------------------------------------------------
extern "C" void kernel_launch(void* const* d_in, const int* in_sizes, int n_in,
                              void* d_out, int out_size) {
    const float* group_features = (const float*)d_in[0];  // (B, G, Dim)
    const float* group_centers  = (const float*)d_in[1];  // (B, G, 3)
    const float* original_pts   = (const float*)d_in[2];  // (B, N, 3)
    const int*   nonzero_idx    = (const int*)d_in[3];    // (N)

    const int N   = in_sizes[3];
    const int B   = in_sizes[2] / (3 * N);
    const int Dim = (int)(3LL * in_sizes[0] / in_sizes[1]);
    const int G   = in_sizes[1] / (3 * B);
    const int HoHo = out_size / (B * Dim);
    int Ho = 1;
    while ((Ho + 1) * (Ho + 1) <= HoHo) Ho++;     // integer sqrt
    const int ks = IMAGE_SIZE / Ho;

    const int nW = B * HoHo * G;

    zero_kernel<<<512, 256>>>(nW);

    dim3 nnGrid((N + 255) / 256, B);
    size_t smem = (size_t)G * sizeof(float4);
    nn_kernel<<<nnGrid, 256, smem>>>(group_centers, original_pts, nonzero_idx,
                                     G, N, Ho, ks);

    dim3 gGrid((HoHo + 63) / 64, (Dim + 63) / 64, B);
    gemm_wmma_kernel<<<gGrid, 128>>>(group_features, (float*)d_out, G, Dim, HoHo);
}